// round 1
// baseline (speedup 1.0000x reference)
#include <cuda_runtime.h>
#include <math.h>

// Problem constants
#define BB   2
#define TT   2048
#define DD   2048
#define NH   16
#define NKV  4
#define HDm  128
#define MROWS (BB*TT)   // 4096

// Scratch (static device allocations; no cudaMalloc allowed)
__device__ float g_q[BB*NH*TT*HDm];    // 8,388,608 floats
__device__ float g_k[BB*NKV*TT*HDm];   // 2,097,152
__device__ float g_v[BB*NKV*TT*HDm];
__device__ float g_ctx[BB*TT*DD];      // 8,388,608

// ---------------------------------------------------------------------------
// Tiled fp32 GEMM: C[M,N] = A[M,K] @ B[K,N]
// BM=BN=128, BK=8, 256 threads, 8x8 register tile per thread.
// MODE 0: C row-major [M,N]
// MODE 1: scatter to (b, h, t, d) layout: m=(b,t), n=(h,d), H = N/128
// ---------------------------------------------------------------------------
template<int MODE>
__global__ void __launch_bounds__(256)
sgemm_k(const float* __restrict__ A, const float* __restrict__ Bm,
        float* __restrict__ C, int M, int N, int K)
{
    __shared__ float As[8][128];
    __shared__ float Bs[8][128];

    const int tid = threadIdx.x;
    const int m0 = blockIdx.y * 128;
    const int n0 = blockIdx.x * 128;
    const int tx = tid & 15;   // 0..15 -> col block
    const int ty = tid >> 4;   // 0..15 -> row block

    const int arow = tid >> 1;        // 0..127
    const int acol = (tid & 1) * 4;   // 0 or 4
    const int brow = tid >> 5;        // 0..7
    const int bcol = (tid & 31) * 4;  // 0..124

    float acc[8][8];
#pragma unroll
    for (int i = 0; i < 8; i++)
#pragma unroll
        for (int j = 0; j < 8; j++) acc[i][j] = 0.f;

    for (int k0 = 0; k0 < K; k0 += 8) {
        float4 av = *(const float4*)&A[(long)(m0 + arow) * K + k0 + acol];
        As[acol + 0][arow] = av.x;
        As[acol + 1][arow] = av.y;
        As[acol + 2][arow] = av.z;
        As[acol + 3][arow] = av.w;
        *(float4*)&Bs[brow][bcol] =
            *(const float4*)&Bm[(long)(k0 + brow) * N + n0 + bcol];
        __syncthreads();

#pragma unroll
        for (int kk = 0; kk < 8; kk++) {
            float4 a0 = *(const float4*)&As[kk][ty * 8];
            float4 a1 = *(const float4*)&As[kk][ty * 8 + 4];
            float4 b0 = *(const float4*)&Bs[kk][tx * 8];
            float4 b1 = *(const float4*)&Bs[kk][tx * 8 + 4];
            float a[8] = {a0.x, a0.y, a0.z, a0.w, a1.x, a1.y, a1.z, a1.w};
            float b[8] = {b0.x, b0.y, b0.z, b0.w, b1.x, b1.y, b1.z, b1.w};
#pragma unroll
            for (int i = 0; i < 8; i++)
#pragma unroll
                for (int j = 0; j < 8; j++)
                    acc[i][j] = fmaf(a[i], b[j], acc[i][j]);
        }
        __syncthreads();
    }

#pragma unroll
    for (int i = 0; i < 8; i++) {
        int m = m0 + ty * 8 + i;
        int n = n0 + tx * 8;
        float4 o0 = make_float4(acc[i][0], acc[i][1], acc[i][2], acc[i][3]);
        float4 o1 = make_float4(acc[i][4], acc[i][5], acc[i][6], acc[i][7]);
        if (MODE == 0) {
            float* cp = C + (long)m * N + n;
            *(float4*)cp = o0;
            *(float4*)(cp + 4) = o1;
        } else {
            int b = m >> 11, t = m & 2047;       // T = 2048
            int h = n >> 7,  d = n & 127;        // HD = 128
            int Hx = N >> 7;
            float* cp = C + ((long)(b * Hx + h) * TT + t) * HDm + d;
            *(float4*)cp = o0;
            *(float4*)(cp + 4) = o1;
        }
    }
}

// ---------------------------------------------------------------------------
// RoPE (in place on (B,Hx,T,128) tensor). One block per (b,h,t) row, 64 threads.
// out[j]    = x[j]*cos - x[j+64]*sin
// out[j+64] = x[j+64]*cos + x[j]*sin        (same angle for the pair)
// ---------------------------------------------------------------------------
__global__ void rope_k(float* __restrict__ p)
{
    int row = blockIdx.x;        // (b*Hx + h)*T + t
    int t = row & 2047;          // T = 2048
    int j = threadIdx.x;         // 0..63
    float e = (float)(2 * j) / 128.0f;
    float inv = 1.0f / powf(10000.0f, e);
    float ang = (float)t * inv;
    float c = cosf(ang), s = sinf(ang);
    float* q = p + (long)row * 128;
    float x1 = q[j], x2 = q[j + 64];
    q[j]      = x1 * c - x2 * s;
    q[j + 64] = x2 * c + x1 * s;
}

// ---------------------------------------------------------------------------
// Causal flash attention, fp32, BQ=BK=64, HD=128, 256 threads.
// Writes directly into (B, T, D) context layout (fused head-permute).
// ---------------------------------------------------------------------------
#define QSTR 132
#define SSTR 65
#define FLASH_SMEM_FLOATS (3 * 64 * QSTR + 64 * SSTR + 3 * 64)
#define FLASH_SMEM_BYTES  (FLASH_SMEM_FLOATS * 4)

__global__ void __launch_bounds__(256)
flash_k(const float* __restrict__ Q, const float* __restrict__ Kp,
        const float* __restrict__ Vp, float* __restrict__ ctx)
{
    extern __shared__ float sm[];
    float* Qs = sm;                       // 64 x 132
    float* Ks = Qs + 64 * QSTR;           // 64 x 132
    float* Vs = Ks + 64 * QSTR;           // 64 x 132
    float* Ss = Vs + 64 * QSTR;           // 64 x 65
    float* mS = Ss + 64 * SSTR;           // 64
    float* lS = mS + 64;                  // 64
    float* aS = lS + 64;                  // 64

    const int tid = threadIdx.x;
    const int qt = blockIdx.x;            // q tile (0..31)
    const int h  = blockIdx.y;            // head
    const int b  = blockIdx.z;            // batch
    const int hk = h >> 2;                // GQA: 4 q heads per kv head
    const float scale = 0.08838834764831845f;  // 1/sqrt(128)

    const float* qg = Q  + ((long)(b * NH  + h ) * TT + qt * 64) * HDm;
    const float* kg = Kp + ((long)(b * NKV + hk) * TT) * HDm;
    const float* vg = Vp + ((long)(b * NKV + hk) * TT) * HDm;

    // Load Q tile (64x128), padded stride
    for (int i = tid; i < 2048; i += 256) {
        int r = i >> 5, c4 = (i & 31) * 4;
        *(float4*)&Qs[r * QSTR + c4] = *(const float4*)&qg[(long)r * HDm + c4];
    }
    if (tid < 64) { mS[tid] = -INFINITY; lS[tid] = 0.f; }

    const int vx = tid & 15;   // col block of 8 (O) / col block of 4 (S)
    const int vy = tid >> 4;   // row block of 4

    float oacc[4][8];
#pragma unroll
    for (int i = 0; i < 4; i++)
#pragma unroll
        for (int j = 0; j < 8; j++) oacc[i][j] = 0.f;

    const int nkt = qt + 1;    // causal: only tiles up to diagonal
    for (int kt = 0; kt < nkt; kt++) {
        __syncthreads();   // prev iter's PV done before overwriting K/V/S
        for (int i = tid; i < 2048; i += 256) {
            int r = i >> 5, c4 = (i & 31) * 4;
            long g = ((long)(kt * 64 + r)) * HDm + c4;
            *(float4*)&Ks[r * QSTR + c4] = *(const float4*)&kg[g];
            *(float4*)&Vs[r * QSTR + c4] = *(const float4*)&vg[g];
        }
        __syncthreads();

        // S = Q @ K^T  (each thread: 4x4 block)
        float sacc[4][4];
#pragma unroll
        for (int i = 0; i < 4; i++)
#pragma unroll
            for (int j = 0; j < 4; j++) sacc[i][j] = 0.f;

        for (int d = 0; d < 128; d += 4) {
            float4 qv[4], kv[4];
#pragma unroll
            for (int i = 0; i < 4; i++)
                qv[i] = *(const float4*)&Qs[(vy * 4 + i) * QSTR + d];
#pragma unroll
            for (int j = 0; j < 4; j++)
                kv[j] = *(const float4*)&Ks[(vx * 4 + j) * QSTR + d];
#pragma unroll
            for (int i = 0; i < 4; i++)
#pragma unroll
                for (int j = 0; j < 4; j++) {
                    sacc[i][j] = fmaf(qv[i].x, kv[j].x, sacc[i][j]);
                    sacc[i][j] = fmaf(qv[i].y, kv[j].y, sacc[i][j]);
                    sacc[i][j] = fmaf(qv[i].z, kv[j].z, sacc[i][j]);
                    sacc[i][j] = fmaf(qv[i].w, kv[j].w, sacc[i][j]);
                }
        }
#pragma unroll
        for (int i = 0; i < 4; i++) {
            int qi = qt * 64 + vy * 4 + i;
#pragma unroll
            for (int j = 0; j < 4; j++) {
                int kj = kt * 64 + vx * 4 + j;
                Ss[(vy * 4 + i) * SSTR + (vx * 4 + j)] =
                    (kj <= qi) ? sacc[i][j] * scale : -INFINITY;
            }
        }
        __syncthreads();

        // Online softmax stats: one thread per row
        if (tid < 64) {
            int r = tid;
            float mx = -INFINITY;
            for (int c = 0; c < 64; c++) mx = fmaxf(mx, Ss[r * SSTR + c]);
            float mold = mS[r];
            float mnew = fmaxf(mold, mx);
            float alpha = __expf(mold - mnew);   // -inf -> 0 on first tile
            float sum = 0.f;
            for (int c = 0; c < 64; c++) {
                float pv = __expf(Ss[r * SSTR + c] - mnew);
                Ss[r * SSTR + c] = pv;
                sum += pv;
            }
            lS[r] = lS[r] * alpha + sum;
            mS[r] = mnew;
            aS[r] = alpha;
        }
        __syncthreads();

        // O = O*alpha + P @ V  (each thread: 4 rows x 8 cols)
#pragma unroll
        for (int i = 0; i < 4; i++) {
            float al = aS[vy * 4 + i];
#pragma unroll
            for (int j = 0; j < 8; j++) oacc[i][j] *= al;
        }
        for (int j = 0; j < 64; j++) {
            float4 v0 = *(const float4*)&Vs[j * QSTR + vx * 8];
            float4 v1 = *(const float4*)&Vs[j * QSTR + vx * 8 + 4];
#pragma unroll
            for (int i = 0; i < 4; i++) {
                float p = Ss[(vy * 4 + i) * SSTR + j];
                oacc[i][0] = fmaf(p, v0.x, oacc[i][0]);
                oacc[i][1] = fmaf(p, v0.y, oacc[i][1]);
                oacc[i][2] = fmaf(p, v0.z, oacc[i][2]);
                oacc[i][3] = fmaf(p, v0.w, oacc[i][3]);
                oacc[i][4] = fmaf(p, v1.x, oacc[i][4]);
                oacc[i][5] = fmaf(p, v1.y, oacc[i][5]);
                oacc[i][6] = fmaf(p, v1.z, oacc[i][6]);
                oacc[i][7] = fmaf(p, v1.w, oacc[i][7]);
            }
        }
    }

    // Normalize and write directly into (B, T, D) context layout.
#pragma unroll
    for (int i = 0; i < 4; i++) {
        int r = vy * 4 + i;
        float linv = 1.0f / lS[r];
        int trow = qt * 64 + r;
        float4 o0 = make_float4(oacc[i][0] * linv, oacc[i][1] * linv,
                                oacc[i][2] * linv, oacc[i][3] * linv);
        float4 o1 = make_float4(oacc[i][4] * linv, oacc[i][5] * linv,
                                oacc[i][6] * linv, oacc[i][7] * linv);
        float* cp = ctx + ((long)(b * TT + trow)) * DD + h * HDm + vx * 8;
        *(float4*)cp = o0;
        *(float4*)(cp + 4) = o1;
    }
}

// ---------------------------------------------------------------------------
extern "C" void kernel_launch(void* const* d_in, const int* in_sizes, int n_in,
                              void* d_out, int out_size)
{
    const float* x  = (const float*)d_in[0];
    const float* wq = (const float*)d_in[1];
    const float* wk = (const float*)d_in[2];
    const float* wv = (const float*)d_in[3];
    const float* wo = (const float*)d_in[4];
    float* out = (float*)d_out;

    float *q, *k, *v, *ctx;
    cudaGetSymbolAddress((void**)&q,   g_q);
    cudaGetSymbolAddress((void**)&k,   g_k);
    cudaGetSymbolAddress((void**)&v,   g_v);
    cudaGetSymbolAddress((void**)&ctx, g_ctx);

    cudaFuncSetAttribute(flash_k, cudaFuncAttributeMaxDynamicSharedMemorySize,
                         FLASH_SMEM_BYTES);

    dim3 blk(256);
    // Projections (scatter into (b,h,t,d) layout)
    sgemm_k<1><<<dim3(16, 32), blk>>>(x, wq, q, MROWS, 2048, DD);
    sgemm_k<1><<<dim3(4, 32),  blk>>>(x, wk, k, MROWS, 512,  DD);
    sgemm_k<1><<<dim3(4, 32),  blk>>>(x, wv, v, MROWS, 512,  DD);

    // RoPE on q and k
    rope_k<<<BB * NH * TT, 64>>>(q);
    rope_k<<<BB * NKV * TT, 64>>>(k);

    // Causal flash attention -> ctx (B,T,D)
    flash_k<<<dim3(TT / 64, NH, BB), 256, FLASH_SMEM_BYTES>>>(q, k, v, ctx);

    // Output projection
    sgemm_k<0><<<dim3(16, 32), blk>>>(ctx, wo, out, MROWS, DD, DD);
}

// round 2
// speedup vs baseline: 1.8956x; 1.8956x over previous
#include <cuda_runtime.h>
#include <math.h>
#include <stdint.h>

// Problem constants
#define BB   2
#define TT   2048
#define DD   2048
#define NH   16
#define NKV  4
#define HDm  128
#define MROWS (BB*TT)   // 4096

// Scratch
__device__ float g_q[BB*NH*TT*HDm];
__device__ float g_k[BB*NKV*TT*HDm];
__device__ float g_v[BB*NKV*TT*HDm];
__device__ float g_ctx[BB*TT*DD];

// ---------------------------------------------------------------------------
// tf32 helpers
// ---------------------------------------------------------------------------
__device__ __forceinline__ uint32_t f2tf(float x) {
    uint32_t r;
    asm("cvt.rna.tf32.f32 %0, %1;" : "=r"(r) : "f"(x));
    return r;
}
__device__ __forceinline__ void split_tf32(float x, uint32_t& h, uint32_t& l) {
    uint32_t hb = f2tf(x);
    float lf = x - __uint_as_float(hb);
    h = hb;
    l = f2tf(lf);
}
__device__ __forceinline__ void mma_tf32(float c[4],
                                         uint32_t a0, uint32_t a1, uint32_t a2, uint32_t a3,
                                         uint32_t b0, uint32_t b1) {
    asm volatile(
        "mma.sync.aligned.m16n8k8.row.col.f32.tf32.tf32.f32 "
        "{%0,%1,%2,%3}, {%4,%5,%6,%7}, {%8,%9}, {%0,%1,%2,%3};\n"
        : "+f"(c[0]), "+f"(c[1]), "+f"(c[2]), "+f"(c[3])
        : "r"(a0), "r"(a1), "r"(a2), "r"(a3), "r"(b0), "r"(b1));
}

// ---------------------------------------------------------------------------
// 3xTF32 tensor-core GEMM: C[M,N] = A[M,K] @ B[K,N]
// BM=BN=128, BK=32, 256 threads (8 warps, 2x4), warp tile 64x32.
// MODE 0: row-major C. MODE 1: scatter to (b,h,t,d), H = N/128.
// ---------------------------------------------------------------------------
#define ASTR 136
template<int MODE>
__global__ void __launch_bounds__(256)
tgemm_k(const float* __restrict__ A, const float* __restrict__ Bm,
        float* __restrict__ C, int M, int N, int K)
{
    __shared__ float As[32 * ASTR];   // [k][m]
    __shared__ float Bs[32 * ASTR];   // [k][n]

    const int tid = threadIdx.x;
    const int lane = tid & 31;
    const int wid = tid >> 5;
    const int warpM = wid & 1;    // 0..1 -> 64-row half
    const int warpN = wid >> 1;   // 0..3 -> 32-col quarter
    const int m0 = blockIdx.y * 128;
    const int n0 = blockIdx.x * 128;

    const int ar = tid >> 3;          // 0..31 (A row within 32-row pass)
    const int ac = (tid & 7) * 4;     // A col group
    const int br = tid >> 5;          // 0..7 (B row within 8-row pass)
    const int bc = (tid & 31) * 4;    // B col group

    float acc[4][4][4];
#pragma unroll
    for (int i = 0; i < 4; i++)
#pragma unroll
        for (int j = 0; j < 4; j++)
#pragma unroll
            for (int r = 0; r < 4; r++) acc[i][j][r] = 0.f;

    float4 pa[4], pb[4];
#pragma unroll
    for (int p = 0; p < 4; p++) {
        pa[p] = *(const float4*)&A[(long)(m0 + ar + p * 32) * K + ac];
        pb[p] = *(const float4*)&Bm[(long)(br + p * 8) * N + n0 + bc];
    }

    for (int k0 = 0; k0 < K; k0 += 32) {
#pragma unroll
        for (int p = 0; p < 4; p++) {
            int m = ar + p * 32;
            As[(ac + 0) * ASTR + m] = pa[p].x;
            As[(ac + 1) * ASTR + m] = pa[p].y;
            As[(ac + 2) * ASTR + m] = pa[p].z;
            As[(ac + 3) * ASTR + m] = pa[p].w;
            *(float4*)&Bs[(br + p * 8) * ASTR + bc] = pb[p];
        }
        __syncthreads();

        if (k0 + 32 < K) {
#pragma unroll
            for (int p = 0; p < 4; p++) {
                pa[p] = *(const float4*)&A[(long)(m0 + ar + p * 32) * K + k0 + 32 + ac];
                pb[p] = *(const float4*)&Bm[(long)(k0 + 32 + br + p * 8) * N + n0 + bc];
            }
        }

#pragma unroll
        for (int ks = 0; ks < 4; ks++) {
            const int kk = ks * 8;
            uint32_t ah[4][4], al[4][4];
#pragma unroll
            for (int mi = 0; mi < 4; mi++) {
                int mA = warpM * 64 + mi * 16 + (lane >> 2);
                int kA = kk + (lane & 3);
                split_tf32(As[kA * ASTR + mA],           ah[mi][0], al[mi][0]);
                split_tf32(As[kA * ASTR + mA + 8],       ah[mi][1], al[mi][1]);
                split_tf32(As[(kA + 4) * ASTR + mA],     ah[mi][2], al[mi][2]);
                split_tf32(As[(kA + 4) * ASTR + mA + 8], ah[mi][3], al[mi][3]);
            }
            uint32_t bh[4][2], bl[4][2];
#pragma unroll
            for (int nt = 0; nt < 4; nt++) {
                int nB = warpN * 32 + nt * 8 + (lane >> 2);
                int kB = kk + (lane & 3);
                split_tf32(Bs[kB * ASTR + nB],       bh[nt][0], bl[nt][0]);
                split_tf32(Bs[(kB + 4) * ASTR + nB], bh[nt][1], bl[nt][1]);
            }
#pragma unroll
            for (int mi = 0; mi < 4; mi++)
#pragma unroll
                for (int nt = 0; nt < 4; nt++) {
                    mma_tf32(acc[mi][nt], ah[mi][0], ah[mi][1], ah[mi][2], ah[mi][3],
                             bh[nt][0], bh[nt][1]);
                    mma_tf32(acc[mi][nt], ah[mi][0], ah[mi][1], ah[mi][2], ah[mi][3],
                             bl[nt][0], bl[nt][1]);
                    mma_tf32(acc[mi][nt], al[mi][0], al[mi][1], al[mi][2], al[mi][3],
                             bh[nt][0], bh[nt][1]);
                }
        }
        __syncthreads();
    }

    // Epilogue
#pragma unroll
    for (int mi = 0; mi < 4; mi++) {
        int r1 = m0 + warpM * 64 + mi * 16 + (lane >> 2);
        int r2 = r1 + 8;
#pragma unroll
        for (int nt = 0; nt < 4; nt++) {
            int c = n0 + warpN * 32 + nt * 8 + (lane & 3) * 2;
            float2 v1 = make_float2(acc[mi][nt][0], acc[mi][nt][1]);
            float2 v2 = make_float2(acc[mi][nt][2], acc[mi][nt][3]);
            if (MODE == 0) {
                *(float2*)&C[(long)r1 * N + c] = v1;
                *(float2*)&C[(long)r2 * N + c] = v2;
            } else {
                int Hx = N >> 7;
                int h = c >> 7, d = c & 127;
                int b1 = r1 >> 11, t1 = r1 & 2047;
                int b2 = r2 >> 11, t2 = r2 & 2047;
                *(float2*)&C[((long)(b1 * Hx + h) * TT + t1) * HDm + d] = v1;
                *(float2*)&C[((long)(b2 * Hx + h) * TT + t2) * HDm + d] = v2;
            }
        }
    }
}

// ---------------------------------------------------------------------------
// RoPE (in place on (B,Hx,T,128)).
// ---------------------------------------------------------------------------
__global__ void rope_k(float* __restrict__ p)
{
    int row = blockIdx.x;
    int t = row & 2047;
    int j = threadIdx.x;          // 0..63
    float e = (float)(2 * j) / 128.0f;
    float inv = 1.0f / powf(10000.0f, e);
    float ang = (float)t * inv;
    float c = cosf(ang), s = sinf(ang);
    float* q = p + (long)row * 128;
    float x1 = q[j], x2 = q[j + 64];
    q[j]      = x1 * c - x2 * s;
    q[j + 64] = x2 * c + x1 * s;
}

// ---------------------------------------------------------------------------
// Causal flash attention, tf32 tensor cores. BQ=BK=64, HD=128, 256 threads.
// Warp grid for S: (warpM=wid&3 over 64 rows) x (warpN=wid>>2 over 2x32 cols).
// Warp grid for O: same warpM, warpN over 2x64 cols.
// ---------------------------------------------------------------------------
#define QSTR 132
#define SSTR 68
#define FLASH_SMEM_FLOATS (3 * 64 * QSTR + 64 * SSTR + 3 * 64)
#define FLASH_SMEM_BYTES  (FLASH_SMEM_FLOATS * 4)

__global__ void __launch_bounds__(256)
flash_k(const float* __restrict__ Q, const float* __restrict__ Kp,
        const float* __restrict__ Vp, float* __restrict__ ctx)
{
    extern __shared__ float sm[];
    float* Qs = sm;                       // 64 x 132 (row-major [t][d])
    float* Ks = Qs + 64 * QSTR;           // 64 x 132
    float* Vs = Ks + 64 * QSTR;           // 64 x 132
    float* Ss = Vs + 64 * QSTR;           // 64 x 68
    float* mS = Ss + 64 * SSTR;
    float* lS = mS + 64;
    float* aS = lS + 64;

    const int tid = threadIdx.x;
    const int lane = tid & 31;
    const int wid = tid >> 5;
    const int warpM = wid & 3;    // 16-row slice
    const int warpN = wid >> 2;   // 0..1
    const int qt = blockIdx.x;
    const int h  = blockIdx.y;
    const int b  = blockIdx.z;
    const int hk = h >> 2;
    const float scale = 0.08838834764831845f;

    const float* qg = Q  + ((long)(b * NH  + h ) * TT + qt * 64) * HDm;
    const float* kg = Kp + ((long)(b * NKV + hk) * TT) * HDm;
    const float* vg = Vp + ((long)(b * NKV + hk) * TT) * HDm;

    for (int i = tid; i < 2048; i += 256) {
        int r = i >> 5, c4 = (i & 31) * 4;
        *(float4*)&Qs[r * QSTR + c4] = *(const float4*)&qg[(long)r * HDm + c4];
    }
    if (tid < 64) { mS[tid] = -INFINITY; lS[tid] = 0.f; }

    float oacc[8][4];
#pragma unroll
    for (int nt = 0; nt < 8; nt++)
#pragma unroll
        for (int r = 0; r < 4; r++) oacc[nt][r] = 0.f;

    const int mrow = warpM * 16 + (lane >> 2);   // S/O row (first of pair)
    const int nkt = qt + 1;

    for (int kt = 0; kt < nkt; kt++) {
        __syncthreads();
        for (int i = tid; i < 2048; i += 256) {
            int r = i >> 5, c4 = (i & 31) * 4;
            long g = ((long)(kt * 64 + r)) * HDm + c4;
            *(float4*)&Ks[r * QSTR + c4] = *(const float4*)&kg[g];
            *(float4*)&Vs[r * QSTR + c4] = *(const float4*)&vg[g];
        }
        __syncthreads();

        // ---- S = Q @ K^T (tf32) ----
        float sfrag[4][4];
#pragma unroll
        for (int nt = 0; nt < 4; nt++)
#pragma unroll
            for (int r = 0; r < 4; r++) sfrag[nt][r] = 0.f;

#pragma unroll
        for (int ks = 0; ks < 16; ks++) {
            const int kk = ks * 8 + (lane & 3);
            uint32_t a0 = f2tf(Qs[mrow * QSTR + kk]);
            uint32_t a1 = f2tf(Qs[(mrow + 8) * QSTR + kk]);
            uint32_t a2 = f2tf(Qs[mrow * QSTR + kk + 4]);
            uint32_t a3 = f2tf(Qs[(mrow + 8) * QSTR + kk + 4]);
#pragma unroll
            for (int nt = 0; nt < 4; nt++) {
                int nrow = warpN * 32 + nt * 8 + (lane >> 2);
                uint32_t b0 = f2tf(Ks[nrow * QSTR + kk]);
                uint32_t b1 = f2tf(Ks[nrow * QSTR + kk + 4]);
                mma_tf32(sfrag[nt], a0, a1, a2, a3, b0, b1);
            }
        }

        // mask + scale -> Ss
        const int qi1 = qt * 64 + mrow;
        const int qi2 = qi1 + 8;
#pragma unroll
        for (int nt = 0; nt < 4; nt++) {
            int cloc = warpN * 32 + nt * 8 + (lane & 3) * 2;
            int kj = kt * 64 + cloc;
            float v0 = (kj     <= qi1) ? sfrag[nt][0] * scale : -INFINITY;
            float v1 = (kj + 1 <= qi1) ? sfrag[nt][1] * scale : -INFINITY;
            float v2 = (kj     <= qi2) ? sfrag[nt][2] * scale : -INFINITY;
            float v3 = (kj + 1 <= qi2) ? sfrag[nt][3] * scale : -INFINITY;
            Ss[mrow * SSTR + cloc] = v0;
            Ss[mrow * SSTR + cloc + 1] = v1;
            Ss[(mrow + 8) * SSTR + cloc] = v2;
            Ss[(mrow + 8) * SSTR + cloc + 1] = v3;
        }
        __syncthreads();

        // ---- online softmax: 4 lanes per row ----
        {
            int r = tid >> 2;
            int part = (tid & 3) * 16;
            float mx = -INFINITY;
#pragma unroll
            for (int i = 0; i < 16; i++)
                mx = fmaxf(mx, Ss[r * SSTR + part + i]);
            mx = fmaxf(mx, __shfl_xor_sync(0xffffffffu, mx, 1));
            mx = fmaxf(mx, __shfl_xor_sync(0xffffffffu, mx, 2));
            float mold = mS[r];
            float mnew = fmaxf(mold, mx);
            float sum = 0.f;
#pragma unroll
            for (int i = 0; i < 16; i++) {
                float pv = __expf(Ss[r * SSTR + part + i] - mnew);
                Ss[r * SSTR + part + i] = pv;
                sum += pv;
            }
            sum += __shfl_xor_sync(0xffffffffu, sum, 1);
            sum += __shfl_xor_sync(0xffffffffu, sum, 2);
            if ((tid & 3) == 0) {
                float alpha = __expf(mold - mnew);
                lS[r] = lS[r] * alpha + sum;
                mS[r] = mnew;
                aS[r] = alpha;
            }
        }
        __syncthreads();

        // ---- rescale O, then O += P @ V ----
        float al1 = aS[mrow], al2 = aS[mrow + 8];
#pragma unroll
        for (int nt = 0; nt < 8; nt++) {
            oacc[nt][0] *= al1; oacc[nt][1] *= al1;
            oacc[nt][2] *= al2; oacc[nt][3] *= al2;
        }
#pragma unroll
        for (int ks = 0; ks < 8; ks++) {
            const int kk = ks * 8 + (lane & 3);
            uint32_t a0 = f2tf(Ss[mrow * SSTR + kk]);
            uint32_t a1 = f2tf(Ss[(mrow + 8) * SSTR + kk]);
            uint32_t a2 = f2tf(Ss[mrow * SSTR + kk + 4]);
            uint32_t a3 = f2tf(Ss[(mrow + 8) * SSTR + kk + 4]);
#pragma unroll
            for (int nt = 0; nt < 8; nt++) {
                int n = warpN * 64 + nt * 8 + (lane >> 2);
                uint32_t b0 = f2tf(Vs[kk * QSTR + n]);
                uint32_t b1 = f2tf(Vs[(kk + 4) * QSTR + n]);
                mma_tf32(oacc[nt], a0, a1, a2, a3, b0, b1);
            }
        }
    }

    // normalize + write to (B,T,D)
    float li1 = 1.0f / lS[mrow];
    float li2 = 1.0f / lS[mrow + 8];
    int t1 = qt * 64 + mrow;
    int t2 = t1 + 8;
#pragma unroll
    for (int nt = 0; nt < 8; nt++) {
        int n = warpN * 64 + nt * 8 + (lane & 3) * 2;
        float2 v1 = make_float2(oacc[nt][0] * li1, oacc[nt][1] * li1);
        float2 v2 = make_float2(oacc[nt][2] * li2, oacc[nt][3] * li2);
        *(float2*)&ctx[((long)(b * TT + t1)) * DD + h * HDm + n] = v1;
        *(float2*)&ctx[((long)(b * TT + t2)) * DD + h * HDm + n] = v2;
    }
}

// ---------------------------------------------------------------------------
extern "C" void kernel_launch(void* const* d_in, const int* in_sizes, int n_in,
                              void* d_out, int out_size)
{
    const float* x  = (const float*)d_in[0];
    const float* wq = (const float*)d_in[1];
    const float* wk = (const float*)d_in[2];
    const float* wv = (const float*)d_in[3];
    const float* wo = (const float*)d_in[4];
    float* out = (float*)d_out;

    float *q, *k, *v, *ctx;
    cudaGetSymbolAddress((void**)&q,   g_q);
    cudaGetSymbolAddress((void**)&k,   g_k);
    cudaGetSymbolAddress((void**)&v,   g_v);
    cudaGetSymbolAddress((void**)&ctx, g_ctx);

    cudaFuncSetAttribute(flash_k, cudaFuncAttributeMaxDynamicSharedMemorySize,
                         FLASH_SMEM_BYTES);

    dim3 blk(256);
    tgemm_k<1><<<dim3(16, 32), blk>>>(x, wq, q, MROWS, 2048, DD);
    tgemm_k<1><<<dim3(4, 32),  blk>>>(x, wk, k, MROWS, 512,  DD);
    tgemm_k<1><<<dim3(4, 32),  blk>>>(x, wv, v, MROWS, 512,  DD);

    rope_k<<<BB * NH * TT, 64>>>(q);
    rope_k<<<BB * NKV * TT, 64>>>(k);

    flash_k<<<dim3(TT / 64, NH, BB), 256, FLASH_SMEM_BYTES>>>(q, k, v, ctx);

    tgemm_k<0><<<dim3(16, 32), blk>>>(ctx, wo, out, MROWS, DD, DD);
}

// round 3
// speedup vs baseline: 2.2021x; 1.1617x over previous
#include <cuda_runtime.h>
#include <math.h>
#include <stdint.h>

// Problem constants
#define BB   2
#define TT   2048
#define DD   2048
#define NH   16
#define NKV  4
#define HDm  128
#define MROWS (BB*TT)   // 4096

// Scratch
__device__ float g_q[BB*NH*TT*HDm];
__device__ float g_k[BB*NKV*TT*HDm];
__device__ float g_v[BB*NKV*TT*HDm];
__device__ float g_ctx[BB*TT*DD];

// ---------------------------------------------------------------------------
// tf32 helpers
// ---------------------------------------------------------------------------
__device__ __forceinline__ uint32_t f2tf(float x) {
    uint32_t r;
    asm("cvt.rna.tf32.f32 %0, %1;" : "=r"(r) : "f"(x));
    return r;
}
__device__ __forceinline__ void split_tf32(float x, uint32_t& h, uint32_t& l) {
    uint32_t hb = f2tf(x);
    float lf = x - __uint_as_float(hb);
    h = hb;
    l = f2tf(lf);
}
__device__ __forceinline__ float ex2(float x) {
    float y;
    asm("ex2.approx.f32 %0, %1;" : "=f"(y) : "f"(x));
    return y;
}
__device__ __forceinline__ void mma_tf32(float c[4],
                                         uint32_t a0, uint32_t a1, uint32_t a2, uint32_t a3,
                                         uint32_t b0, uint32_t b1) {
    asm volatile(
        "mma.sync.aligned.m16n8k8.row.col.f32.tf32.tf32.f32 "
        "{%0,%1,%2,%3}, {%4,%5,%6,%7}, {%8,%9}, {%0,%1,%2,%3};\n"
        : "+f"(c[0]), "+f"(c[1]), "+f"(c[2]), "+f"(c[3])
        : "r"(a0), "r"(a1), "r"(a2), "r"(a3), "r"(b0), "r"(b1));
}

// ---------------------------------------------------------------------------
// 3xTF32 GEMM with pre-split hi/lo smem planes + double buffering.
// BM=BN=128, BK=16, 128 threads (4 warps), warp tile 64x64.
// A smem: [m][k] stride 20 (u32, conflict-free). B smem: [k][n] stride 136.
// MODE 0: row-major C. MODE 1: scatter to (b,h,t,d), H = N/128.
// ---------------------------------------------------------------------------
#define AST 20
#define BST 136
#define A_SZ (128 * AST)            // 2560 u32
#define B_SZ (16 * BST)             // 2176 u32
#define GBUF (2 * A_SZ + 2 * B_SZ)  // 9472 u32
#define GEMM_SMEM_BYTES (2 * GBUF * 4)

template<int MODE>
__global__ void __launch_bounds__(128, 2)
tgemm_k(const float* __restrict__ A, const float* __restrict__ Bm,
        float* __restrict__ C, int M, int N, int K)
{
    extern __shared__ uint32_t gsm[];

    const int tid = threadIdx.x;
    const int lane = tid & 31;
    const int wid = tid >> 5;      // 0..3
    const int warpM = wid & 1;     // 64-row half
    const int warpN = wid >> 1;    // 64-col half
    const int m0 = blockIdx.y * 128;
    const int n0 = blockIdx.x * 128;

    const int arow = tid >> 2;        // 0..31 (+p*32)
    const int acol = (tid & 3) * 4;   // 0,4,8,12
    const int brow = tid >> 5;        // 0..3  (+p*4)
    const int bcol = (tid & 31) * 4;  // 0..124

    float acc[4][8][4];
#pragma unroll
    for (int i = 0; i < 4; i++)
#pragma unroll
        for (int j = 0; j < 8; j++)
#pragma unroll
            for (int r = 0; r < 4; r++) acc[i][j][r] = 0.f;

    float4 ra[4], rb[4];
#pragma unroll
    for (int p = 0; p < 4; p++) {
        ra[p] = *(const float4*)&A[(long)(m0 + arow + p * 32) * K + acol];
        rb[p] = *(const float4*)&Bm[(long)(brow + p * 4) * N + n0 + bcol];
    }

    const int NKT = K / 16;
    for (int kt = 0; kt < NKT; kt++) {
        uint32_t* Ah = gsm + (kt & 1) * GBUF;
        uint32_t* Al = Ah + A_SZ;
        uint32_t* Bh = Al + A_SZ;
        uint32_t* Bl = Bh + B_SZ;

        // split + store to smem
#pragma unroll
        for (int p = 0; p < 4; p++) {
            int r = arow + p * 32;
            uint4 h, l;
            split_tf32(ra[p].x, h.x, l.x);
            split_tf32(ra[p].y, h.y, l.y);
            split_tf32(ra[p].z, h.z, l.z);
            split_tf32(ra[p].w, h.w, l.w);
            *(uint4*)&Ah[r * AST + acol] = h;
            *(uint4*)&Al[r * AST + acol] = l;
        }
#pragma unroll
        for (int p = 0; p < 4; p++) {
            int r = brow + p * 4;
            uint4 h, l;
            split_tf32(rb[p].x, h.x, l.x);
            split_tf32(rb[p].y, h.y, l.y);
            split_tf32(rb[p].z, h.z, l.z);
            split_tf32(rb[p].w, h.w, l.w);
            *(uint4*)&Bh[r * BST + bcol] = h;
            *(uint4*)&Bl[r * BST + bcol] = l;
        }
        __syncthreads();

        if (kt + 1 < NKT) {
            int k0 = (kt + 1) * 16;
#pragma unroll
            for (int p = 0; p < 4; p++) {
                ra[p] = *(const float4*)&A[(long)(m0 + arow + p * 32) * K + k0 + acol];
                rb[p] = *(const float4*)&Bm[(long)(k0 + brow + p * 4) * N + n0 + bcol];
            }
        }

#pragma unroll
        for (int ks = 0; ks < 2; ks++) {
            const int kk = ks * 8 + (lane & 3);
            uint32_t ah[4][4], al[4][4];
#pragma unroll
            for (int mi = 0; mi < 4; mi++) {
                int m = warpM * 64 + mi * 16 + (lane >> 2);
                ah[mi][0] = Ah[m * AST + kk];
                ah[mi][1] = Ah[(m + 8) * AST + kk];
                ah[mi][2] = Ah[m * AST + kk + 4];
                ah[mi][3] = Ah[(m + 8) * AST + kk + 4];
                al[mi][0] = Al[m * AST + kk];
                al[mi][1] = Al[(m + 8) * AST + kk];
                al[mi][2] = Al[m * AST + kk + 4];
                al[mi][3] = Al[(m + 8) * AST + kk + 4];
            }
#pragma unroll
            for (int nt = 0; nt < 8; nt++) {
                int n = warpN * 64 + nt * 8 + (lane >> 2);
                uint32_t b0h = Bh[kk * BST + n];
                uint32_t b1h = Bh[(kk + 4) * BST + n];
                uint32_t b0l = Bl[kk * BST + n];
                uint32_t b1l = Bl[(kk + 4) * BST + n];
#pragma unroll
                for (int mi = 0; mi < 4; mi++) {
                    mma_tf32(acc[mi][nt], ah[mi][0], ah[mi][1], ah[mi][2], ah[mi][3], b0h, b1h);
                    mma_tf32(acc[mi][nt], ah[mi][0], ah[mi][1], ah[mi][2], ah[mi][3], b0l, b1l);
                    mma_tf32(acc[mi][nt], al[mi][0], al[mi][1], al[mi][2], al[mi][3], b0h, b1h);
                }
            }
        }
        __syncthreads();
    }

    // Epilogue
#pragma unroll
    for (int mi = 0; mi < 4; mi++) {
        int r1 = m0 + warpM * 64 + mi * 16 + (lane >> 2);
        int r2 = r1 + 8;
#pragma unroll
        for (int nt = 0; nt < 8; nt++) {
            int c = n0 + warpN * 64 + nt * 8 + (lane & 3) * 2;
            float2 v1 = make_float2(acc[mi][nt][0], acc[mi][nt][1]);
            float2 v2 = make_float2(acc[mi][nt][2], acc[mi][nt][3]);
            if (MODE == 0) {
                *(float2*)&C[(long)r1 * N + c] = v1;
                *(float2*)&C[(long)r2 * N + c] = v2;
            } else {
                int Hx = N >> 7;
                int h = c >> 7, d = c & 127;
                int b1 = r1 >> 11, t1 = r1 & 2047;
                int b2 = r2 >> 11, t2 = r2 & 2047;
                *(float2*)&C[((long)(b1 * Hx + h) * TT + t1) * HDm + d] = v1;
                *(float2*)&C[((long)(b2 * Hx + h) * TT + t2) * HDm + d] = v2;
            }
        }
    }
}

// ---------------------------------------------------------------------------
// RoPE (in place on (B,Hx,T,128)).
// ---------------------------------------------------------------------------
__global__ void rope_k(float* __restrict__ p)
{
    int row = blockIdx.x;
    int t = row & 2047;
    int j = threadIdx.x;          // 0..63
    float e = (float)(2 * j) / 128.0f;
    float inv = 1.0f / powf(10000.0f, e);
    float ang = (float)t * inv;
    float c = cosf(ang), s = sinf(ang);
    float* q = p + (long)row * 128;
    float x1 = q[j], x2 = q[j + 64];
    q[j]      = x1 * c - x2 * s;
    q[j + 64] = x2 * c + x1 * s;
}

// ---------------------------------------------------------------------------
// Causal flash attention, tf32 tensor cores, pre-converted operands in smem.
// BQ=BK=64, HD=128, 256 threads. Scores carried in log2 domain
// (scale*log2e folded into Q), softmax via raw EX2.
// ---------------------------------------------------------------------------
#define QSTR 132
#define SSTR 68
#define FLASH_SMEM_FLOATS (3 * 64 * QSTR + 64 * SSTR + 3 * 64)
#define FLASH_SMEM_BYTES  (FLASH_SMEM_FLOATS * 4)
#define SCALE_LOG2E 0.12751744709274227f   // (1/sqrt(128)) * log2(e)

__global__ void __launch_bounds__(256)
flash_k(const float* __restrict__ Q, const float* __restrict__ Kp,
        const float* __restrict__ Vp, float* __restrict__ ctx)
{
    extern __shared__ float sm[];
    float* Qs = sm;                       // 64 x 132 [t][d], tf32-valued
    float* Ks = Qs + 64 * QSTR;           // 64 x 132, tf32-valued
    float* Vs = Ks + 64 * QSTR;           // 64 x 132, tf32-valued
    float* Ss = Vs + 64 * QSTR;           // 64 x 68
    float* mS = Ss + 64 * SSTR;
    float* lS = mS + 64;
    float* aS = lS + 64;

    const int tid = threadIdx.x;
    const int lane = tid & 31;
    const int wid = tid >> 5;
    const int warpM = wid & 3;    // 16-row slice
    const int warpN = wid >> 2;   // 0..1
    const int qt = blockIdx.x;
    const int h  = blockIdx.y;
    const int b  = blockIdx.z;
    const int hk = h >> 2;

    const float* qg = Q  + ((long)(b * NH  + h ) * TT + qt * 64) * HDm;
    const float* kg = Kp + ((long)(b * NKV + hk) * TT) * HDm;
    const float* vg = Vp + ((long)(b * NKV + hk) * TT) * HDm;

    // Q: fold scale*log2e, convert to tf32 once
    for (int i = tid; i < 2048; i += 256) {
        int r = i >> 5, c4 = (i & 31) * 4;
        float4 v = *(const float4*)&qg[(long)r * HDm + c4];
        float4 o;
        o.x = __uint_as_float(f2tf(v.x * SCALE_LOG2E));
        o.y = __uint_as_float(f2tf(v.y * SCALE_LOG2E));
        o.z = __uint_as_float(f2tf(v.z * SCALE_LOG2E));
        o.w = __uint_as_float(f2tf(v.w * SCALE_LOG2E));
        *(float4*)&Qs[r * QSTR + c4] = o;
    }
    if (tid < 64) { mS[tid] = -INFINITY; lS[tid] = 0.f; }

    float oacc[8][4];
#pragma unroll
    for (int nt = 0; nt < 8; nt++)
#pragma unroll
        for (int r = 0; r < 4; r++) oacc[nt][r] = 0.f;

    const int mrow = warpM * 16 + (lane >> 2);
    const int nkt = qt + 1;

    for (int kt = 0; kt < nkt; kt++) {
        __syncthreads();
        for (int i = tid; i < 2048; i += 256) {
            int r = i >> 5, c4 = (i & 31) * 4;
            long g = ((long)(kt * 64 + r)) * HDm + c4;
            float4 kv = *(const float4*)&kg[g];
            float4 vv = *(const float4*)&vg[g];
            float4 ko, vo;
            ko.x = __uint_as_float(f2tf(kv.x));
            ko.y = __uint_as_float(f2tf(kv.y));
            ko.z = __uint_as_float(f2tf(kv.z));
            ko.w = __uint_as_float(f2tf(kv.w));
            vo.x = __uint_as_float(f2tf(vv.x));
            vo.y = __uint_as_float(f2tf(vv.y));
            vo.z = __uint_as_float(f2tf(vv.z));
            vo.w = __uint_as_float(f2tf(vv.w));
            *(float4*)&Ks[r * QSTR + c4] = ko;
            *(float4*)&Vs[r * QSTR + c4] = vo;
        }
        __syncthreads();

        // ---- S = Q @ K^T (log2-domain scores) ----
        float sfrag[4][4];
#pragma unroll
        for (int nt = 0; nt < 4; nt++)
#pragma unroll
            for (int r = 0; r < 4; r++) sfrag[nt][r] = 0.f;

#pragma unroll
        for (int ks = 0; ks < 16; ks++) {
            const int kk = ks * 8 + (lane & 3);
            uint32_t a0 = __float_as_uint(Qs[mrow * QSTR + kk]);
            uint32_t a1 = __float_as_uint(Qs[(mrow + 8) * QSTR + kk]);
            uint32_t a2 = __float_as_uint(Qs[mrow * QSTR + kk + 4]);
            uint32_t a3 = __float_as_uint(Qs[(mrow + 8) * QSTR + kk + 4]);
#pragma unroll
            for (int nt = 0; nt < 4; nt++) {
                int nrow = warpN * 32 + nt * 8 + (lane >> 2);
                uint32_t b0 = __float_as_uint(Ks[nrow * QSTR + kk]);
                uint32_t b1 = __float_as_uint(Ks[nrow * QSTR + kk + 4]);
                mma_tf32(sfrag[nt], a0, a1, a2, a3, b0, b1);
            }
        }

        // mask -> Ss (scores already scaled, log2 domain)
        const int qi1 = qt * 64 + mrow;
        const int qi2 = qi1 + 8;
#pragma unroll
        for (int nt = 0; nt < 4; nt++) {
            int cloc = warpN * 32 + nt * 8 + (lane & 3) * 2;
            int kj = kt * 64 + cloc;
            Ss[mrow * SSTR + cloc]           = (kj     <= qi1) ? sfrag[nt][0] : -INFINITY;
            Ss[mrow * SSTR + cloc + 1]       = (kj + 1 <= qi1) ? sfrag[nt][1] : -INFINITY;
            Ss[(mrow + 8) * SSTR + cloc]     = (kj     <= qi2) ? sfrag[nt][2] : -INFINITY;
            Ss[(mrow + 8) * SSTR + cloc + 1] = (kj + 1 <= qi2) ? sfrag[nt][3] : -INFINITY;
        }
        __syncthreads();

        // ---- online softmax (base-2), 4 lanes per row; P stored tf32 ----
        {
            int r = tid >> 2;
            int part = (tid & 3) * 16;
            float mx = -INFINITY;
#pragma unroll
            for (int i = 0; i < 16; i++)
                mx = fmaxf(mx, Ss[r * SSTR + part + i]);
            mx = fmaxf(mx, __shfl_xor_sync(0xffffffffu, mx, 1));
            mx = fmaxf(mx, __shfl_xor_sync(0xffffffffu, mx, 2));
            float mold = mS[r];
            float mnew = fmaxf(mold, mx);
            float sum = 0.f;
#pragma unroll
            for (int i = 0; i < 16; i++) {
                float pv = ex2(Ss[r * SSTR + part + i] - mnew);
                float pvr = __uint_as_float(f2tf(pv));
                Ss[r * SSTR + part + i] = pvr;
                sum += pvr;
            }
            sum += __shfl_xor_sync(0xffffffffu, sum, 1);
            sum += __shfl_xor_sync(0xffffffffu, sum, 2);
            if ((tid & 3) == 0) {
                float alpha = ex2(mold - mnew);
                lS[r] = lS[r] * alpha + sum;
                mS[r] = mnew;
                aS[r] = alpha;
            }
        }
        __syncthreads();

        // ---- O = O*alpha + P @ V ----
        float al1 = aS[mrow], al2 = aS[mrow + 8];
#pragma unroll
        for (int nt = 0; nt < 8; nt++) {
            oacc[nt][0] *= al1; oacc[nt][1] *= al1;
            oacc[nt][2] *= al2; oacc[nt][3] *= al2;
        }
#pragma unroll
        for (int ks = 0; ks < 8; ks++) {
            const int kk = ks * 8 + (lane & 3);
            uint32_t a0 = __float_as_uint(Ss[mrow * SSTR + kk]);
            uint32_t a1 = __float_as_uint(Ss[(mrow + 8) * SSTR + kk]);
            uint32_t a2 = __float_as_uint(Ss[mrow * SSTR + kk + 4]);
            uint32_t a3 = __float_as_uint(Ss[(mrow + 8) * SSTR + kk + 4]);
#pragma unroll
            for (int nt = 0; nt < 8; nt++) {
                int n = warpN * 64 + nt * 8 + (lane >> 2);
                uint32_t b0 = __float_as_uint(Vs[kk * QSTR + n]);
                uint32_t b1 = __float_as_uint(Vs[(kk + 4) * QSTR + n]);
                mma_tf32(oacc[nt], a0, a1, a2, a3, b0, b1);
            }
        }
    }

    // normalize + write to (B,T,D)
    float li1 = 1.0f / lS[mrow];
    float li2 = 1.0f / lS[mrow + 8];
    int t1 = qt * 64 + mrow;
    int t2 = t1 + 8;
#pragma unroll
    for (int nt = 0; nt < 8; nt++) {
        int n = warpN * 64 + nt * 8 + (lane & 3) * 2;
        float2 v1 = make_float2(oacc[nt][0] * li1, oacc[nt][1] * li1);
        float2 v2 = make_float2(oacc[nt][2] * li2, oacc[nt][3] * li2);
        *(float2*)&ctx[((long)(b * TT + t1)) * DD + h * HDm + n] = v1;
        *(float2*)&ctx[((long)(b * TT + t2)) * DD + h * HDm + n] = v2;
    }
}

// ---------------------------------------------------------------------------
extern "C" void kernel_launch(void* const* d_in, const int* in_sizes, int n_in,
                              void* d_out, int out_size)
{
    const float* x  = (const float*)d_in[0];
    const float* wq = (const float*)d_in[1];
    const float* wk = (const float*)d_in[2];
    const float* wv = (const float*)d_in[3];
    const float* wo = (const float*)d_in[4];
    float* out = (float*)d_out;

    float *q, *k, *v, *ctx;
    cudaGetSymbolAddress((void**)&q,   g_q);
    cudaGetSymbolAddress((void**)&k,   g_k);
    cudaGetSymbolAddress((void**)&v,   g_v);
    cudaGetSymbolAddress((void**)&ctx, g_ctx);

    cudaFuncSetAttribute(tgemm_k<0>, cudaFuncAttributeMaxDynamicSharedMemorySize,
                         GEMM_SMEM_BYTES);
    cudaFuncSetAttribute(tgemm_k<1>, cudaFuncAttributeMaxDynamicSharedMemorySize,
                         GEMM_SMEM_BYTES);
    cudaFuncSetAttribute(flash_k, cudaFuncAttributeMaxDynamicSharedMemorySize,
                         FLASH_SMEM_BYTES);

    dim3 blk(128);
    tgemm_k<1><<<dim3(16, 32), blk, GEMM_SMEM_BYTES>>>(x, wq, q, MROWS, 2048, DD);
    tgemm_k<1><<<dim3(4, 32),  blk, GEMM_SMEM_BYTES>>>(x, wk, k, MROWS, 512,  DD);
    tgemm_k<1><<<dim3(4, 32),  blk, GEMM_SMEM_BYTES>>>(x, wv, v, MROWS, 512,  DD);

    rope_k<<<BB * NH * TT, 64>>>(q);
    rope_k<<<BB * NKV * TT, 64>>>(k);

    flash_k<<<dim3(TT / 64, NH, BB), 256, FLASH_SMEM_BYTES>>>(q, k, v, ctx);

    tgemm_k<0><<<dim3(16, 32), blk, GEMM_SMEM_BYTES>>>(ctx, wo, out, MROWS, DD, DD);
}

// round 4
// speedup vs baseline: 4.2961x; 1.9509x over previous
#include <cuda_runtime.h>
#include <math.h>
#include <stdint.h>

// Problem constants
#define BB   2
#define TT   2048
#define DD   2048
#define NH   16
#define NKV  4
#define HDm  128
#define MROWS (BB*TT)   // 4096

// Scratch
__device__ float g_q[BB*NH*TT*HDm];
__device__ float g_k[BB*NKV*TT*HDm];
__device__ float g_v[BB*NKV*TT*HDm];
__device__ float g_ctx[BB*TT*DD];
__device__ float g_rope[TT*128];       // [t][0..63]=cos, [t][64..127]=sin

// ---------------------------------------------------------------------------
// helpers
// ---------------------------------------------------------------------------
__device__ __forceinline__ uint32_t f2tf(float x) {
    uint32_t r;
    asm("cvt.rna.tf32.f32 %0, %1;" : "=r"(r) : "f"(x));
    return r;
}
__device__ __forceinline__ float ex2(float x) {
    float y;
    asm("ex2.approx.f32 %0, %1;" : "=f"(y) : "f"(x));
    return y;
}
__device__ __forceinline__ void mma_tf32(float c[4],
                                         uint32_t a0, uint32_t a1, uint32_t a2, uint32_t a3,
                                         uint32_t b0, uint32_t b1) {
    asm volatile(
        "mma.sync.aligned.m16n8k8.row.col.f32.tf32.tf32.f32 "
        "{%0,%1,%2,%3}, {%4,%5,%6,%7}, {%8,%9}, {%0,%1,%2,%3};\n"
        : "+f"(c[0]), "+f"(c[1]), "+f"(c[2]), "+f"(c[3])
        : "r"(a0), "r"(a1), "r"(a2), "r"(a3), "r"(b0), "r"(b1));
}

// ---------------------------------------------------------------------------
// 1xTF32 GEMM: C[M,N] = A[M,K] @ B[K,N]
// BM=BN=128, BK=32, 128 threads (4 warps), warp tile 64x64, double-buffered.
// A smem [m][k] stride 36 (conflict-free), B smem [k][n] stride 136.
// MODE 0: row-major C. MODE 1: scatter to (b,h,t,d), H = N/128.
// ---------------------------------------------------------------------------
#define AST 36
#define BST 136
#define A_SZ (128 * AST)            // 4608 u32
#define B_SZ (32 * BST)             // 4352 u32
#define GBUF (A_SZ + B_SZ)          // 8960 u32
#define GEMM_SMEM_BYTES (2 * GBUF * 4)

template<int MODE>
__global__ void __launch_bounds__(128, 2)
tgemm_k(const float* __restrict__ A, const float* __restrict__ Bm,
        float* __restrict__ C, int M, int N, int K)
{
    extern __shared__ uint32_t gsm[];

    const int tid = threadIdx.x;
    const int lane = tid & 31;
    const int wid = tid >> 5;      // 0..3
    const int warpM = wid & 1;     // 64-row half
    const int warpN = wid >> 1;    // 64-col half
    const int m0 = blockIdx.y * 128;
    const int n0 = blockIdx.x * 128;

    const int arow = tid >> 3;        // 0..15 (+p*16)
    const int acol = (tid & 7) * 4;   // 0..28
    const int brow = tid >> 5;        // 0..3  (+p*4)
    const int bcol = (tid & 31) * 4;  // 0..124

    float acc[4][8][4];
#pragma unroll
    for (int i = 0; i < 4; i++)
#pragma unroll
        for (int j = 0; j < 8; j++)
#pragma unroll
            for (int r = 0; r < 4; r++) acc[i][j][r] = 0.f;

    float4 ra[8], rb[8];
#pragma unroll
    for (int p = 0; p < 8; p++) {
        ra[p] = *(const float4*)&A[(long)(m0 + arow + p * 16) * K + acol];
        rb[p] = *(const float4*)&Bm[(long)(brow + p * 4) * N + n0 + bcol];
    }

    const int NKT = K / 32;
    for (int kt = 0; kt < NKT; kt++) {
        uint32_t* As = gsm + (kt & 1) * GBUF;
        uint32_t* Bs = As + A_SZ;

#pragma unroll
        for (int p = 0; p < 8; p++) {
            int m = arow + p * 16;
            uint4 h;
            h.x = f2tf(ra[p].x); h.y = f2tf(ra[p].y);
            h.z = f2tf(ra[p].z); h.w = f2tf(ra[p].w);
            *(uint4*)&As[m * AST + acol] = h;
        }
#pragma unroll
        for (int p = 0; p < 8; p++) {
            int r = brow + p * 4;
            uint4 h;
            h.x = f2tf(rb[p].x); h.y = f2tf(rb[p].y);
            h.z = f2tf(rb[p].z); h.w = f2tf(rb[p].w);
            *(uint4*)&Bs[r * BST + bcol] = h;
        }
        __syncthreads();

        if (kt + 1 < NKT) {
            int k0 = (kt + 1) * 32;
#pragma unroll
            for (int p = 0; p < 8; p++) {
                ra[p] = *(const float4*)&A[(long)(m0 + arow + p * 16) * K + k0 + acol];
                rb[p] = *(const float4*)&Bm[(long)(k0 + brow + p * 4) * N + n0 + bcol];
            }
        }

#pragma unroll
        for (int ks = 0; ks < 4; ks++) {
            const int kk = ks * 8 + (lane & 3);
            uint32_t af[4][4];
#pragma unroll
            for (int mi = 0; mi < 4; mi++) {
                int m = warpM * 64 + mi * 16 + (lane >> 2);
                af[mi][0] = As[m * AST + kk];
                af[mi][1] = As[(m + 8) * AST + kk];
                af[mi][2] = As[m * AST + kk + 4];
                af[mi][3] = As[(m + 8) * AST + kk + 4];
            }
#pragma unroll
            for (int nt = 0; nt < 8; nt++) {
                int n = warpN * 64 + nt * 8 + (lane >> 2);
                uint32_t b0 = Bs[kk * BST + n];
                uint32_t b1 = Bs[(kk + 4) * BST + n];
#pragma unroll
                for (int mi = 0; mi < 4; mi++)
                    mma_tf32(acc[mi][nt], af[mi][0], af[mi][1], af[mi][2], af[mi][3], b0, b1);
            }
        }
        __syncthreads();
    }

    // Epilogue
#pragma unroll
    for (int mi = 0; mi < 4; mi++) {
        int r1 = m0 + warpM * 64 + mi * 16 + (lane >> 2);
        int r2 = r1 + 8;
#pragma unroll
        for (int nt = 0; nt < 8; nt++) {
            int c = n0 + warpN * 64 + nt * 8 + (lane & 3) * 2;
            float2 v1 = make_float2(acc[mi][nt][0], acc[mi][nt][1]);
            float2 v2 = make_float2(acc[mi][nt][2], acc[mi][nt][3]);
            if (MODE == 0) {
                *(float2*)&C[(long)r1 * N + c] = v1;
                *(float2*)&C[(long)r2 * N + c] = v2;
            } else {
                int Hx = N >> 7;
                int h = c >> 7, d = c & 127;
                int b1 = r1 >> 11, t1 = r1 & 2047;
                int b2 = r2 >> 11, t2 = r2 & 2047;
                *(float2*)&C[((long)(b1 * Hx + h) * TT + t1) * HDm + d] = v1;
                *(float2*)&C[((long)(b2 * Hx + h) * TT + t2) * HDm + d] = v2;
            }
        }
    }
}

// ---------------------------------------------------------------------------
// RoPE: table build + apply
// ---------------------------------------------------------------------------
__global__ void rope_table_k(float* __restrict__ tab)
{
    int t = blockIdx.x;
    int j = threadIdx.x;   // 0..63
    // inv_freq = 10000^(-j/64) = 2^(-j*log2(10000)/64)
    float inv = exp2f(-(float)j * (13.287712379549449f / 64.0f));
    float ang = (float)t * inv;
    tab[t * 128 + j]      = cosf(ang);
    tab[t * 128 + 64 + j] = sinf(ang);
}

__global__ void rope_k(float* __restrict__ p, const float* __restrict__ tab)
{
    int row = blockIdx.x * 4 + (threadIdx.x >> 6);
    int j = threadIdx.x & 63;
    int t = row & 2047;
    float c = tab[t * 128 + j];
    float s = tab[t * 128 + 64 + j];
    float* q = p + (long)row * 128;
    float x1 = q[j], x2 = q[j + 64];
    q[j]      = x1 * c - x2 * s;
    q[j + 64] = x2 * c + x1 * s;
}

// ---------------------------------------------------------------------------
// Causal flash attention, tf32, BQ=64, BK=32, HD=128, 256 threads, 2 CTA/SM.
// Scores in log2 domain (scale*log2e folded into Q); softmax via EX2.
// ---------------------------------------------------------------------------
#define QSTR 132
#define KST  132
#define VST  136
#define SSTR 36
#define FLASH_SMEM_FLOATS (64 * QSTR + 32 * KST + 32 * VST + 64 * SSTR + 3 * 64)
#define FLASH_SMEM_BYTES  (FLASH_SMEM_FLOATS * 4)
#define SCALE_LOG2E 0.12751744709274227f   // (1/sqrt(128)) * log2(e)

__global__ void __launch_bounds__(256, 2)
flash_k(const float* __restrict__ Q, const float* __restrict__ Kp,
        const float* __restrict__ Vp, float* __restrict__ ctx)
{
    extern __shared__ float sm[];
    float* Qs = sm;                       // 64 x 132, tf32-valued, pre-scaled
    float* Ks = Qs + 64 * QSTR;           // 32 x 132, tf32-valued
    float* Vs = Ks + 32 * KST;            // 32 x 136, tf32-valued
    float* Ss = Vs + 32 * VST;            // 64 x 36
    float* mS = Ss + 64 * SSTR;
    float* lS = mS + 64;
    float* aS = lS + 64;

    const int tid = threadIdx.x;
    const int lane = tid & 31;
    const int wid = tid >> 5;
    const int warpM = wid & 3;    // 16-row slice of 64
    const int warpN = wid >> 2;   // 0..1
    const int qt = blockIdx.x;
    const int h  = blockIdx.y;
    const int b  = blockIdx.z;
    const int hk = h >> 2;

    const float* qg = Q  + ((long)(b * NH  + h ) * TT + qt * 64) * HDm;
    const float* kg = Kp + ((long)(b * NKV + hk) * TT) * HDm;
    const float* vg = Vp + ((long)(b * NKV + hk) * TT) * HDm;

    // Q: fold scale*log2e, convert to tf32 once
    for (int i = tid; i < 2048; i += 256) {
        int r = i >> 5, c4 = (i & 31) * 4;
        float4 v = *(const float4*)&qg[(long)r * HDm + c4];
        float4 o;
        o.x = __uint_as_float(f2tf(v.x * SCALE_LOG2E));
        o.y = __uint_as_float(f2tf(v.y * SCALE_LOG2E));
        o.z = __uint_as_float(f2tf(v.z * SCALE_LOG2E));
        o.w = __uint_as_float(f2tf(v.w * SCALE_LOG2E));
        *(float4*)&Qs[r * QSTR + c4] = o;
    }
    if (tid < 64) { mS[tid] = -INFINITY; lS[tid] = 0.f; }

    float oacc[8][4];
#pragma unroll
    for (int nt = 0; nt < 8; nt++)
#pragma unroll
        for (int r = 0; r < 4; r++) oacc[nt][r] = 0.f;

    const int mrow = warpM * 16 + (lane >> 2);
    const int nkt = 2 * qt + 2;

    for (int kt = 0; kt < nkt; kt++) {
        __syncthreads();
        // Load K/V tile (32 x 128)
        for (int i = tid; i < 1024; i += 256) {
            int r = i >> 5, c4 = (i & 31) * 4;
            long g = ((long)(kt * 32 + r)) * HDm + c4;
            float4 kv = *(const float4*)&kg[g];
            float4 vv = *(const float4*)&vg[g];
            float4 ko, vo;
            ko.x = __uint_as_float(f2tf(kv.x));
            ko.y = __uint_as_float(f2tf(kv.y));
            ko.z = __uint_as_float(f2tf(kv.z));
            ko.w = __uint_as_float(f2tf(kv.w));
            vo.x = __uint_as_float(f2tf(vv.x));
            vo.y = __uint_as_float(f2tf(vv.y));
            vo.z = __uint_as_float(f2tf(vv.z));
            vo.w = __uint_as_float(f2tf(vv.w));
            *(float4*)&Ks[r * KST + c4] = ko;
            *(float4*)&Vs[r * VST + c4] = vo;
        }
        __syncthreads();

        // ---- S = Q @ K^T : 64x32, warp tile 16x16 ----
        float sfrag[2][4];
#pragma unroll
        for (int nt = 0; nt < 2; nt++)
#pragma unroll
            for (int r = 0; r < 4; r++) sfrag[nt][r] = 0.f;

#pragma unroll
        for (int ks = 0; ks < 16; ks++) {
            const int kk = ks * 8 + (lane & 3);
            uint32_t a0 = __float_as_uint(Qs[mrow * QSTR + kk]);
            uint32_t a1 = __float_as_uint(Qs[(mrow + 8) * QSTR + kk]);
            uint32_t a2 = __float_as_uint(Qs[mrow * QSTR + kk + 4]);
            uint32_t a3 = __float_as_uint(Qs[(mrow + 8) * QSTR + kk + 4]);
#pragma unroll
            for (int nt = 0; nt < 2; nt++) {
                int nrow = warpN * 16 + nt * 8 + (lane >> 2);
                uint32_t b0 = __float_as_uint(Ks[nrow * KST + kk]);
                uint32_t b1 = __float_as_uint(Ks[nrow * KST + kk + 4]);
                mma_tf32(sfrag[nt], a0, a1, a2, a3, b0, b1);
            }
        }

        // mask -> Ss (log2 domain, pre-scaled)
        const int qi1 = qt * 64 + mrow;
        const int qi2 = qi1 + 8;
#pragma unroll
        for (int nt = 0; nt < 2; nt++) {
            int cloc = warpN * 16 + nt * 8 + (lane & 3) * 2;
            int kj = kt * 32 + cloc;
            Ss[mrow * SSTR + cloc]           = (kj     <= qi1) ? sfrag[nt][0] : -INFINITY;
            Ss[mrow * SSTR + cloc + 1]       = (kj + 1 <= qi1) ? sfrag[nt][1] : -INFINITY;
            Ss[(mrow + 8) * SSTR + cloc]     = (kj     <= qi2) ? sfrag[nt][2] : -INFINITY;
            Ss[(mrow + 8) * SSTR + cloc + 1] = (kj + 1 <= qi2) ? sfrag[nt][3] : -INFINITY;
        }
        __syncthreads();

        // ---- online softmax (base-2), 4 lanes x 8 cols per row ----
        {
            int r = tid >> 2;
            int part = (tid & 3) * 8;
            float mx = -INFINITY;
#pragma unroll
            for (int i = 0; i < 8; i++)
                mx = fmaxf(mx, Ss[r * SSTR + part + i]);
            mx = fmaxf(mx, __shfl_xor_sync(0xffffffffu, mx, 1));
            mx = fmaxf(mx, __shfl_xor_sync(0xffffffffu, mx, 2));
            float mold = mS[r];
            float mnew = fmaxf(mold, mx);
            float sum = 0.f;
#pragma unroll
            for (int i = 0; i < 8; i++) {
                float pv = ex2(Ss[r * SSTR + part + i] - mnew);
                float pvr = __uint_as_float(f2tf(pv));
                Ss[r * SSTR + part + i] = pvr;
                sum += pvr;
            }
            sum += __shfl_xor_sync(0xffffffffu, sum, 1);
            sum += __shfl_xor_sync(0xffffffffu, sum, 2);
            if ((tid & 3) == 0) {
                float alpha = ex2(mold - mnew);
                lS[r] = lS[r] * alpha + sum;
                mS[r] = mnew;
                aS[r] = alpha;
            }
        }
        __syncthreads();

        // ---- O = O*alpha + P @ V ----
        float al1 = aS[mrow], al2 = aS[mrow + 8];
#pragma unroll
        for (int nt = 0; nt < 8; nt++) {
            oacc[nt][0] *= al1; oacc[nt][1] *= al1;
            oacc[nt][2] *= al2; oacc[nt][3] *= al2;
        }
#pragma unroll
        for (int ks = 0; ks < 4; ks++) {
            const int kk = ks * 8 + (lane & 3);
            uint32_t a0 = __float_as_uint(Ss[mrow * SSTR + kk]);
            uint32_t a1 = __float_as_uint(Ss[(mrow + 8) * SSTR + kk]);
            uint32_t a2 = __float_as_uint(Ss[mrow * SSTR + kk + 4]);
            uint32_t a3 = __float_as_uint(Ss[(mrow + 8) * SSTR + kk + 4]);
#pragma unroll
            for (int nt = 0; nt < 8; nt++) {
                int n = warpN * 64 + nt * 8 + (lane >> 2);
                uint32_t b0 = __float_as_uint(Vs[kk * VST + n]);
                uint32_t b1 = __float_as_uint(Vs[(kk + 4) * VST + n]);
                mma_tf32(oacc[nt], a0, a1, a2, a3, b0, b1);
            }
        }
    }

    // normalize + write to (B,T,D)
    float li1 = 1.0f / lS[mrow];
    float li2 = 1.0f / lS[mrow + 8];
    int t1 = qt * 64 + mrow;
    int t2 = t1 + 8;
#pragma unroll
    for (int nt = 0; nt < 8; nt++) {
        int n = warpN * 64 + nt * 8 + (lane & 3) * 2;
        float2 v1 = make_float2(oacc[nt][0] * li1, oacc[nt][1] * li1);
        float2 v2 = make_float2(oacc[nt][2] * li2, oacc[nt][3] * li2);
        *(float2*)&ctx[((long)(b * TT + t1)) * DD + h * HDm + n] = v1;
        *(float2*)&ctx[((long)(b * TT + t2)) * DD + h * HDm + n] = v2;
    }
}

// ---------------------------------------------------------------------------
extern "C" void kernel_launch(void* const* d_in, const int* in_sizes, int n_in,
                              void* d_out, int out_size)
{
    const float* x  = (const float*)d_in[0];
    const float* wq = (const float*)d_in[1];
    const float* wk = (const float*)d_in[2];
    const float* wv = (const float*)d_in[3];
    const float* wo = (const float*)d_in[4];
    float* out = (float*)d_out;

    float *q, *k, *v, *ctx, *tab;
    cudaGetSymbolAddress((void**)&q,   g_q);
    cudaGetSymbolAddress((void**)&k,   g_k);
    cudaGetSymbolAddress((void**)&v,   g_v);
    cudaGetSymbolAddress((void**)&ctx, g_ctx);
    cudaGetSymbolAddress((void**)&tab, g_rope);

    cudaFuncSetAttribute(tgemm_k<0>, cudaFuncAttributeMaxDynamicSharedMemorySize,
                         GEMM_SMEM_BYTES);
    cudaFuncSetAttribute(tgemm_k<1>, cudaFuncAttributeMaxDynamicSharedMemorySize,
                         GEMM_SMEM_BYTES);
    cudaFuncSetAttribute(flash_k, cudaFuncAttributeMaxDynamicSharedMemorySize,
                         FLASH_SMEM_BYTES);

    rope_table_k<<<TT, 64>>>(tab);

    dim3 blk(128);
    tgemm_k<1><<<dim3(16, 32), blk, GEMM_SMEM_BYTES>>>(x, wq, q, MROWS, 2048, DD);
    tgemm_k<1><<<dim3(4, 32),  blk, GEMM_SMEM_BYTES>>>(x, wk, k, MROWS, 512,  DD);
    tgemm_k<1><<<dim3(4, 32),  blk, GEMM_SMEM_BYTES>>>(x, wv, v, MROWS, 512,  DD);

    rope_k<<<BB * NH * TT / 4, 256>>>(q, tab);
    rope_k<<<BB * NKV * TT / 4, 256>>>(k, tab);

    flash_k<<<dim3(TT / 64, NH, BB), 256, FLASH_SMEM_BYTES>>>(q, k, v, ctx);

    tgemm_k<0><<<dim3(16, 32), blk, GEMM_SMEM_BYTES>>>(ctx, wo, out, MROWS, DD, DD);
}

// round 5
// speedup vs baseline: 4.9785x; 1.1588x over previous
#include <cuda_runtime.h>
#include <math.h>
#include <stdint.h>

// Problem constants
#define BB   2
#define TT   2048
#define DD   2048
#define NH   16
#define NKV  4
#define HDm  128
#define MROWS (BB*TT)   // 4096

// Scratch
__device__ float g_q[BB*NH*TT*HDm];
__device__ float g_k[BB*NKV*TT*HDm];
__device__ float g_v[BB*NKV*TT*HDm];
__device__ float g_ctx[BB*TT*DD];
__device__ float g_rope[TT*128];       // [t][0..63]=cos, [t][64..127]=sin

// ---------------------------------------------------------------------------
// helpers
// ---------------------------------------------------------------------------
__device__ __forceinline__ uint32_t f2tf(float x) {
    uint32_t r;
    asm("cvt.rna.tf32.f32 %0, %1;" : "=r"(r) : "f"(x));
    return r;
}
__device__ __forceinline__ float ex2(float x) {
    float y;
    asm("ex2.approx.f32 %0, %1;" : "=f"(y) : "f"(x));
    return y;
}
__device__ __forceinline__ void mma_tf32(float c[4],
                                         uint32_t a0, uint32_t a1, uint32_t a2, uint32_t a3,
                                         uint32_t b0, uint32_t b1) {
    asm volatile(
        "mma.sync.aligned.m16n8k8.row.col.f32.tf32.tf32.f32 "
        "{%0,%1,%2,%3}, {%4,%5,%6,%7}, {%8,%9}, {%0,%1,%2,%3};\n"
        : "+f"(c[0]), "+f"(c[1]), "+f"(c[2]), "+f"(c[3])
        : "r"(a0), "r"(a1), "r"(a2), "r"(a3), "r"(b0), "r"(b1));
}

// ---------------------------------------------------------------------------
// 1xTF32 GEMM core (BM=BN=128, BK=32, 128 thr, warp tile 64x64, dbl-buffered)
// ---------------------------------------------------------------------------
#define AST 36
#define BST 136
#define A_SZ (128 * AST)
#define B_SZ (32 * BST)
#define GBUF (A_SZ + B_SZ)
#define GEMM_SMEM_BYTES (2 * GBUF * 4)

// Fused QKV projection: blockIdx.x selects {wq: 0..15, wk: 16..19, wv: 20..23}.
__global__ void __launch_bounds__(128, 2)
tqkv_k(const float* __restrict__ A,
       const float* __restrict__ wq, const float* __restrict__ wk,
       const float* __restrict__ wv,
       float* __restrict__ qo, float* __restrict__ ko, float* __restrict__ vo)
{
    extern __shared__ uint32_t gsm[];

    const int bx = blockIdx.x;
    const float* Bm;
    float* C;
    int N, n0, Hx;
    if (bx < 16)      { Bm = wq; C = qo; N = 2048; n0 = bx * 128;        Hx = 16; }
    else if (bx < 20) { Bm = wk; C = ko; N = 512;  n0 = (bx - 16) * 128; Hx = 4;  }
    else              { Bm = wv; C = vo; N = 512;  n0 = (bx - 20) * 128; Hx = 4;  }
    const int K = DD;

    const int tid = threadIdx.x;
    const int lane = tid & 31;
    const int wid = tid >> 5;
    const int warpM = wid & 1;
    const int warpN = wid >> 1;
    const int m0 = blockIdx.y * 128;

    const int arow = tid >> 3;
    const int acol = (tid & 7) * 4;
    const int brow = tid >> 5;
    const int bcol = (tid & 31) * 4;

    float acc[4][8][4];
#pragma unroll
    for (int i = 0; i < 4; i++)
#pragma unroll
        for (int j = 0; j < 8; j++)
#pragma unroll
            for (int r = 0; r < 4; r++) acc[i][j][r] = 0.f;

    float4 ra[8], rb[8];
#pragma unroll
    for (int p = 0; p < 8; p++) {
        ra[p] = *(const float4*)&A[(long)(m0 + arow + p * 16) * K + acol];
        rb[p] = *(const float4*)&Bm[(long)(brow + p * 4) * N + n0 + bcol];
    }

    const int NKT = K / 32;
    for (int kt = 0; kt < NKT; kt++) {
        uint32_t* As = gsm + (kt & 1) * GBUF;
        uint32_t* Bs = As + A_SZ;

#pragma unroll
        for (int p = 0; p < 8; p++) {
            int m = arow + p * 16;
            uint4 h;
            h.x = f2tf(ra[p].x); h.y = f2tf(ra[p].y);
            h.z = f2tf(ra[p].z); h.w = f2tf(ra[p].w);
            *(uint4*)&As[m * AST + acol] = h;
        }
#pragma unroll
        for (int p = 0; p < 8; p++) {
            int r = brow + p * 4;
            uint4 h;
            h.x = f2tf(rb[p].x); h.y = f2tf(rb[p].y);
            h.z = f2tf(rb[p].z); h.w = f2tf(rb[p].w);
            *(uint4*)&Bs[r * BST + bcol] = h;
        }
        __syncthreads();

        if (kt + 1 < NKT) {
            int k0 = (kt + 1) * 32;
#pragma unroll
            for (int p = 0; p < 8; p++) {
                ra[p] = *(const float4*)&A[(long)(m0 + arow + p * 16) * K + k0 + acol];
                rb[p] = *(const float4*)&Bm[(long)(k0 + brow + p * 4) * N + n0 + bcol];
            }
        }

#pragma unroll
        for (int ks = 0; ks < 4; ks++) {
            const int kk = ks * 8 + (lane & 3);
            uint32_t af[4][4];
#pragma unroll
            for (int mi = 0; mi < 4; mi++) {
                int m = warpM * 64 + mi * 16 + (lane >> 2);
                af[mi][0] = As[m * AST + kk];
                af[mi][1] = As[(m + 8) * AST + kk];
                af[mi][2] = As[m * AST + kk + 4];
                af[mi][3] = As[(m + 8) * AST + kk + 4];
            }
#pragma unroll
            for (int nt = 0; nt < 8; nt++) {
                int n = warpN * 64 + nt * 8 + (lane >> 2);
                uint32_t b0 = Bs[kk * BST + n];
                uint32_t b1 = Bs[(kk + 4) * BST + n];
#pragma unroll
                for (int mi = 0; mi < 4; mi++)
                    mma_tf32(acc[mi][nt], af[mi][0], af[mi][1], af[mi][2], af[mi][3], b0, b1);
            }
        }
        __syncthreads();
    }

#pragma unroll
    for (int mi = 0; mi < 4; mi++) {
        int r1 = m0 + warpM * 64 + mi * 16 + (lane >> 2);
        int r2 = r1 + 8;
#pragma unroll
        for (int nt = 0; nt < 8; nt++) {
            int c = n0 + warpN * 64 + nt * 8 + (lane & 3) * 2;
            int h = c >> 7, d = c & 127;
            int b1 = r1 >> 11, t1 = r1 & 2047;
            int b2 = r2 >> 11, t2 = r2 & 2047;
            *(float2*)&C[((long)(b1 * Hx + h) * TT + t1) * HDm + d] =
                make_float2(acc[mi][nt][0], acc[mi][nt][1]);
            *(float2*)&C[((long)(b2 * Hx + h) * TT + t2) * HDm + d] =
                make_float2(acc[mi][nt][2], acc[mi][nt][3]);
        }
    }
}

// Plain GEMM for output projection (row-major C).
__global__ void __launch_bounds__(128, 2)
tgemm_k(const float* __restrict__ A, const float* __restrict__ Bm,
        float* __restrict__ C, int M, int N, int K)
{
    extern __shared__ uint32_t gsm[];

    const int tid = threadIdx.x;
    const int lane = tid & 31;
    const int wid = tid >> 5;
    const int warpM = wid & 1;
    const int warpN = wid >> 1;
    const int m0 = blockIdx.y * 128;
    const int n0 = blockIdx.x * 128;

    const int arow = tid >> 3;
    const int acol = (tid & 7) * 4;
    const int brow = tid >> 5;
    const int bcol = (tid & 31) * 4;

    float acc[4][8][4];
#pragma unroll
    for (int i = 0; i < 4; i++)
#pragma unroll
        for (int j = 0; j < 8; j++)
#pragma unroll
            for (int r = 0; r < 4; r++) acc[i][j][r] = 0.f;

    float4 ra[8], rb[8];
#pragma unroll
    for (int p = 0; p < 8; p++) {
        ra[p] = *(const float4*)&A[(long)(m0 + arow + p * 16) * K + acol];
        rb[p] = *(const float4*)&Bm[(long)(brow + p * 4) * N + n0 + bcol];
    }

    const int NKT = K / 32;
    for (int kt = 0; kt < NKT; kt++) {
        uint32_t* As = gsm + (kt & 1) * GBUF;
        uint32_t* Bs = As + A_SZ;

#pragma unroll
        for (int p = 0; p < 8; p++) {
            int m = arow + p * 16;
            uint4 h;
            h.x = f2tf(ra[p].x); h.y = f2tf(ra[p].y);
            h.z = f2tf(ra[p].z); h.w = f2tf(ra[p].w);
            *(uint4*)&As[m * AST + acol] = h;
        }
#pragma unroll
        for (int p = 0; p < 8; p++) {
            int r = brow + p * 4;
            uint4 h;
            h.x = f2tf(rb[p].x); h.y = f2tf(rb[p].y);
            h.z = f2tf(rb[p].z); h.w = f2tf(rb[p].w);
            *(uint4*)&Bs[r * BST + bcol] = h;
        }
        __syncthreads();

        if (kt + 1 < NKT) {
            int k0 = (kt + 1) * 32;
#pragma unroll
            for (int p = 0; p < 8; p++) {
                ra[p] = *(const float4*)&A[(long)(m0 + arow + p * 16) * K + k0 + acol];
                rb[p] = *(const float4*)&Bm[(long)(k0 + brow + p * 4) * N + n0 + bcol];
            }
        }

#pragma unroll
        for (int ks = 0; ks < 4; ks++) {
            const int kk = ks * 8 + (lane & 3);
            uint32_t af[4][4];
#pragma unroll
            for (int mi = 0; mi < 4; mi++) {
                int m = warpM * 64 + mi * 16 + (lane >> 2);
                af[mi][0] = As[m * AST + kk];
                af[mi][1] = As[(m + 8) * AST + kk];
                af[mi][2] = As[m * AST + kk + 4];
                af[mi][3] = As[(m + 8) * AST + kk + 4];
            }
#pragma unroll
            for (int nt = 0; nt < 8; nt++) {
                int n = warpN * 64 + nt * 8 + (lane >> 2);
                uint32_t b0 = Bs[kk * BST + n];
                uint32_t b1 = Bs[(kk + 4) * BST + n];
#pragma unroll
                for (int mi = 0; mi < 4; mi++)
                    mma_tf32(acc[mi][nt], af[mi][0], af[mi][1], af[mi][2], af[mi][3], b0, b1);
            }
        }
        __syncthreads();
    }

#pragma unroll
    for (int mi = 0; mi < 4; mi++) {
        int r1 = m0 + warpM * 64 + mi * 16 + (lane >> 2);
        int r2 = r1 + 8;
#pragma unroll
        for (int nt = 0; nt < 8; nt++) {
            int c = n0 + warpN * 64 + nt * 8 + (lane & 3) * 2;
            *(float2*)&C[(long)r1 * N + c] = make_float2(acc[mi][nt][0], acc[mi][nt][1]);
            *(float2*)&C[(long)r2 * N + c] = make_float2(acc[mi][nt][2], acc[mi][nt][3]);
        }
    }
}

// ---------------------------------------------------------------------------
// RoPE: table build + fused apply (q then k)
// ---------------------------------------------------------------------------
__global__ void rope_table_k(float* __restrict__ tab)
{
    int t = blockIdx.x;
    int j = threadIdx.x;
    float inv = exp2f(-(float)j * (13.287712379549449f / 64.0f));
    float ang = (float)t * inv;
    tab[t * 128 + j]      = cosf(ang);
    tab[t * 128 + 64 + j] = sinf(ang);
}

#define QROWS (BB*NH*TT)
#define KROWS (BB*NKV*TT)
__global__ void rope2_k(float* __restrict__ qp, float* __restrict__ kp,
                        const float* __restrict__ tab)
{
    int row = blockIdx.x * 4 + (threadIdx.x >> 6);
    int j = threadIdx.x & 63;
    float* p;
    int r;
    if (row < QROWS) { p = qp; r = row; }
    else             { p = kp; r = row - QROWS; }
    int t = r & 2047;
    float c = tab[t * 128 + j];
    float s = tab[t * 128 + 64 + j];
    float* q = p + (long)r * 128;
    float x1 = q[j], x2 = q[j + 64];
    q[j]      = x1 * c - x2 * s;
    q[j + 64] = x2 * c + x1 * s;
}

// ---------------------------------------------------------------------------
// Causal flash attention v2: BQ=128, BK=32, 256 threads (8 warps).
// Warp w owns rows 16w..16w+15. Q frags + S + softmax stats live in registers.
// K/V double-buffered in smem (1 syncthreads/tile). P via warp-private smem.
// Scores in log2 domain (scale*log2e folded into Q).
// ---------------------------------------------------------------------------
#define KST 132
#define VST 136
#define PST 36
#define FK_QS   (128 * KST)                 // Q staging pane (phase A)
#define FK_KOFF 0
#define FK_VOFF (2 * 32 * KST)
#define FK_POFF (FK_VOFF + 2 * 32 * VST)
#define FK_FLOATS_B (FK_POFF + 128 * PST)
#define FLASH_SMEM_FLOATS (FK_QS > FK_FLOATS_B ? FK_QS : FK_FLOATS_B)
#define FLASH_SMEM_BYTES  (FLASH_SMEM_FLOATS * 4)
#define SCALE_LOG2E 0.12751744709274227f   // (1/sqrt(128)) * log2(e)

__global__ void __launch_bounds__(256, 1)
flash_k(const float* __restrict__ Q, const float* __restrict__ Kp,
        const float* __restrict__ Vp, float* __restrict__ ctx)
{
    extern __shared__ float sm[];

    const int tid = threadIdx.x;
    const int lane = tid & 31;
    const int w = tid >> 5;            // warp 0..7
    const int quad = lane >> 2;        // 0..7
    const int j = lane & 3;            // 0..3
    const int qt = gridDim.x - 1 - blockIdx.x;   // big tiles first
    const int h  = blockIdx.y;
    const int b  = blockIdx.z;
    const int hk = h >> 2;

    const float* qg = Q  + ((long)(b * NH  + h ) * TT + qt * 128) * HDm;
    const float* kg = Kp + ((long)(b * NKV + hk) * TT) * HDm;
    const float* vg = Vp + ((long)(b * NKV + hk) * TT) * HDm;

    // ---- Phase A: stage Q (scaled, tf32) in smem, then load frags to regs ----
    {
        float* Qs = sm;
        for (int i = tid; i < 128 * 32; i += 256) {
            int r = i >> 5, c4 = (i & 31) * 4;
            float4 v = *(const float4*)&qg[(long)r * HDm + c4];
            float4 o;
            o.x = __uint_as_float(f2tf(v.x * SCALE_LOG2E));
            o.y = __uint_as_float(f2tf(v.y * SCALE_LOG2E));
            o.z = __uint_as_float(f2tf(v.z * SCALE_LOG2E));
            o.w = __uint_as_float(f2tf(v.w * SCALE_LOG2E));
            *(float4*)&Qs[r * KST + c4] = o;
        }
    }
    __syncthreads();

    uint32_t qf[16][4];
    {
        const float* Qs = sm;
        int r = w * 16 + quad;
#pragma unroll
        for (int ks = 0; ks < 16; ks++) {
            int c = ks * 8 + j;
            qf[ks][0] = __float_as_uint(Qs[r * KST + c]);
            qf[ks][1] = __float_as_uint(Qs[(r + 8) * KST + c]);
            qf[ks][2] = __float_as_uint(Qs[r * KST + c + 4]);
            qf[ks][3] = __float_as_uint(Qs[(r + 8) * KST + c + 4]);
        }
    }
    __syncthreads();   // everyone done reading Qs before K/V overwrite

    float* Ks = sm + FK_KOFF;
    float* Vs = sm + FK_VOFF;
    float* Ps = sm + FK_POFF;

    float oacc[16][4];
#pragma unroll
    for (int nt = 0; nt < 16; nt++)
#pragma unroll
        for (int r = 0; r < 4; r++) oacc[nt][r] = 0.f;

    float m0 = -INFINITY, m1 = -INFINITY, l0 = 0.f, l1 = 0.f;

    const int nkt = 4 * qt + 4;
    const int prow = w * 16 + quad;          // this thread's first row (local)
    const int qi1 = qt * 128 + prow;
    const int qi2 = qi1 + 8;

    // prefetch tile 0
    float4 rk[4], rv[4];
#pragma unroll
    for (int p = 0; p < 4; p++) {
        int idx = tid + p * 256;
        int r = idx >> 5, c4 = (idx & 31) * 4;
        rk[p] = *(const float4*)&kg[(long)r * HDm + c4];
        rv[p] = *(const float4*)&vg[(long)r * HDm + c4];
    }

    for (int kt = 0; kt < nkt; kt++) {
        float* Kb = Ks + (kt & 1) * 32 * KST;
        float* Vb = Vs + (kt & 1) * 32 * VST;

        // store staged tile (converted)
#pragma unroll
        for (int p = 0; p < 4; p++) {
            int idx = tid + p * 256;
            int r = idx >> 5, c4 = (idx & 31) * 4;
            float4 ko, vo;
            ko.x = __uint_as_float(f2tf(rk[p].x));
            ko.y = __uint_as_float(f2tf(rk[p].y));
            ko.z = __uint_as_float(f2tf(rk[p].z));
            ko.w = __uint_as_float(f2tf(rk[p].w));
            vo.x = __uint_as_float(f2tf(rv[p].x));
            vo.y = __uint_as_float(f2tf(rv[p].y));
            vo.z = __uint_as_float(f2tf(rv[p].z));
            vo.w = __uint_as_float(f2tf(rv[p].w));
            *(float4*)&Kb[r * KST + c4] = ko;
            *(float4*)&Vb[r * VST + c4] = vo;
        }
        __syncthreads();

        // prefetch next tile
        if (kt + 1 < nkt) {
#pragma unroll
            for (int p = 0; p < 4; p++) {
                int idx = tid + p * 256;
                int r = idx >> 5, c4 = (idx & 31) * 4;
                long g = ((long)((kt + 1) * 32 + r)) * HDm + c4;
                rk[p] = *(const float4*)&kg[g];
                rv[p] = *(const float4*)&vg[g];
            }
        }

        // ---- S = Q @ K^T  (16x32 per warp, in registers) ----
        float sf[4][4];
#pragma unroll
        for (int nt = 0; nt < 4; nt++)
#pragma unroll
            for (int r = 0; r < 4; r++) sf[nt][r] = 0.f;

#pragma unroll
        for (int ks = 0; ks < 16; ks++) {
            const int kk = ks * 8 + j;
#pragma unroll
            for (int nt = 0; nt < 4; nt++) {
                int key = nt * 8 + quad;
                uint32_t b0 = __float_as_uint(Kb[key * KST + kk]);
                uint32_t b1 = __float_as_uint(Kb[key * KST + kk + 4]);
                mma_tf32(sf[nt], qf[ks][0], qf[ks][1], qf[ks][2], qf[ks][3], b0, b1);
            }
        }

        // ---- causal mask (only last 4 tiles need it) ----
        if (kt >= 4 * qt) {
#pragma unroll
            for (int nt = 0; nt < 4; nt++) {
                int kj = kt * 32 + nt * 8 + 2 * j;
                if (kj     > qi1) sf[nt][0] = -INFINITY;
                if (kj + 1 > qi1) sf[nt][1] = -INFINITY;
                if (kj     > qi2) sf[nt][2] = -INFINITY;
                if (kj + 1 > qi2) sf[nt][3] = -INFINITY;
            }
        }

        // ---- online softmax (base 2), quad reduction ----
        float mx0 = -INFINITY, mx1 = -INFINITY;
#pragma unroll
        for (int nt = 0; nt < 4; nt++) {
            mx0 = fmaxf(mx0, fmaxf(sf[nt][0], sf[nt][1]));
            mx1 = fmaxf(mx1, fmaxf(sf[nt][2], sf[nt][3]));
        }
        mx0 = fmaxf(mx0, __shfl_xor_sync(0xffffffffu, mx0, 1));
        mx0 = fmaxf(mx0, __shfl_xor_sync(0xffffffffu, mx0, 2));
        mx1 = fmaxf(mx1, __shfl_xor_sync(0xffffffffu, mx1, 1));
        mx1 = fmaxf(mx1, __shfl_xor_sync(0xffffffffu, mx1, 2));

        float mn0 = fmaxf(m0, mx0);
        float mn1 = fmaxf(m1, mx1);
        float a0 = ex2(m0 - mn0);
        float a1 = ex2(m1 - mn1);
        m0 = mn0; m1 = mn1;

        float s0 = 0.f, s1 = 0.f;
#pragma unroll
        for (int nt = 0; nt < 4; nt++) {
            float p0 = __uint_as_float(f2tf(ex2(sf[nt][0] - mn0)));
            float p1 = __uint_as_float(f2tf(ex2(sf[nt][1] - mn0)));
            float p2 = __uint_as_float(f2tf(ex2(sf[nt][2] - mn1)));
            float p3 = __uint_as_float(f2tf(ex2(sf[nt][3] - mn1)));
            sf[nt][0] = p0; sf[nt][1] = p1; sf[nt][2] = p2; sf[nt][3] = p3;
            s0 += p0 + p1;
            s1 += p2 + p3;
        }
        s0 += __shfl_xor_sync(0xffffffffu, s0, 1);
        s0 += __shfl_xor_sync(0xffffffffu, s0, 2);
        s1 += __shfl_xor_sync(0xffffffffu, s1, 1);
        s1 += __shfl_xor_sync(0xffffffffu, s1, 2);
        l0 = l0 * a0 + s0;
        l1 = l1 * a1 + s1;

        // rescale O
#pragma unroll
        for (int nt = 0; nt < 16; nt++) {
            oacc[nt][0] *= a0; oacc[nt][1] *= a0;
            oacc[nt][2] *= a1; oacc[nt][3] *= a1;
        }

        // ---- P -> warp-private smem pane ----
#pragma unroll
        for (int nt = 0; nt < 4; nt++) {
            int c = nt * 8 + 2 * j;
            *(float2*)&Ps[prow * PST + c]       = make_float2(sf[nt][0], sf[nt][1]);
            *(float2*)&Ps[(prow + 8) * PST + c] = make_float2(sf[nt][2], sf[nt][3]);
        }
        __syncwarp();

        // ---- O += P @ V ----
#pragma unroll
        for (int kb = 0; kb < 4; kb++) {
            int c = kb * 8 + j;
            uint32_t pa0 = __float_as_uint(Ps[prow * PST + c]);
            uint32_t pa1 = __float_as_uint(Ps[(prow + 8) * PST + c]);
            uint32_t pa2 = __float_as_uint(Ps[prow * PST + c + 4]);
            uint32_t pa3 = __float_as_uint(Ps[(prow + 8) * PST + c + 4]);
#pragma unroll
            for (int nt = 0; nt < 16; nt++) {
                int n = nt * 8 + quad;
                uint32_t b0 = __float_as_uint(Vb[(kb * 8 + j) * VST + n]);
                uint32_t b1 = __float_as_uint(Vb[(kb * 8 + j + 4) * VST + n]);
                mma_tf32(oacc[nt], pa0, pa1, pa2, pa3, b0, b1);
            }
        }
    }

    // ---- normalize + write to (B,T,D) ----
    float li0 = 1.0f / l0;
    float li1 = 1.0f / l1;
    int t1 = qt * 128 + prow;
    int t2 = t1 + 8;
#pragma unroll
    for (int nt = 0; nt < 16; nt++) {
        int n = h * HDm + nt * 8 + 2 * j;
        *(float2*)&ctx[((long)(b * TT + t1)) * DD + n] =
            make_float2(oacc[nt][0] * li0, oacc[nt][1] * li0);
        *(float2*)&ctx[((long)(b * TT + t2)) * DD + n] =
            make_float2(oacc[nt][2] * li1, oacc[nt][3] * li1);
    }
}

// ---------------------------------------------------------------------------
extern "C" void kernel_launch(void* const* d_in, const int* in_sizes, int n_in,
                              void* d_out, int out_size)
{
    const float* x  = (const float*)d_in[0];
    const float* wq = (const float*)d_in[1];
    const float* wk = (const float*)d_in[2];
    const float* wv = (const float*)d_in[3];
    const float* wo = (const float*)d_in[4];
    float* out = (float*)d_out;

    float *q, *k, *v, *ctx, *tab;
    cudaGetSymbolAddress((void**)&q,   g_q);
    cudaGetSymbolAddress((void**)&k,   g_k);
    cudaGetSymbolAddress((void**)&v,   g_v);
    cudaGetSymbolAddress((void**)&ctx, g_ctx);
    cudaGetSymbolAddress((void**)&tab, g_rope);

    cudaFuncSetAttribute(tqkv_k, cudaFuncAttributeMaxDynamicSharedMemorySize,
                         GEMM_SMEM_BYTES);
    cudaFuncSetAttribute(tgemm_k, cudaFuncAttributeMaxDynamicSharedMemorySize,
                         GEMM_SMEM_BYTES);
    cudaFuncSetAttribute(flash_k, cudaFuncAttributeMaxDynamicSharedMemorySize,
                         FLASH_SMEM_BYTES);

    // Fused QKV projection (768 CTAs)
    tqkv_k<<<dim3(24, 32), 128, GEMM_SMEM_BYTES>>>(x, wq, wk, wv, q, k, v);

    rope_table_k<<<TT, 64>>>(tab);
    rope2_k<<<(QROWS + KROWS) / 4, 256>>>(q, k, tab);

    flash_k<<<dim3(TT / 128, NH, BB), 256, FLASH_SMEM_BYTES>>>(q, k, v, ctx);

    tgemm_k<<<dim3(16, 32), 128, GEMM_SMEM_BYTES>>>(ctx, wo, out, MROWS, DD, DD);
}